// round 2
// baseline (speedup 1.0000x reference)
#include <cuda_runtime.h>

#define B_   2
#define C_   128
#define H_   96
#define W_   96
#define HW_  9216     // 96*96
#define NPIX 18432    // B*H*W

// Scratch for q and k (allocation-free rule: __device__ globals)
__device__ __align__(16) float g_q[B_ * C_ * HW_];
__device__ __align__(16) float g_k[B_ * C_ * HW_];

// ---- packed f32x2 helpers (Blackwell full-rate fma pipe) ----
__device__ __forceinline__ void ffma2(unsigned long long& d,
                                      unsigned long long a,
                                      unsigned long long b) {
    asm("fma.rn.f32x2 %0, %1, %2, %0;" : "+l"(d) : "l"(a), "l"(b));
}
__device__ __forceinline__ void unpack2(float& lo, float& hi, unsigned long long v) {
    asm("mov.b64 {%0, %1}, %2;" : "=f"(lo), "=f"(hi) : "l"(v));
}

// ---------------------------------------------------------------------------
// Kernel 1: q = Wq @ x, k = Wk @ x   (1x1 convs as GEMM over pixels)
// f32x2-packed over the co dimension.
// Block: 32 pixels x 128 co x both matrices. 256 threads.
// Thread = (2 co-pairs = 4 co) x (4 px), 16 f32x2 accumulators.
// Weights pre-packed as float2{co0,co1} in smem; x duplicated {x,x} in smem.
// ---------------------------------------------------------------------------
__global__ __launch_bounds__(256) void qk_gemm_kernel(
    const float* __restrict__ x,
    const float* __restrict__ wq,
    const float* __restrict__ wk)
{
    __shared__ __align__(16) float2 swq[64 * 33];  // [cp][ci_local], pad 33
    __shared__ __align__(16) float2 swk[64 * 33];
    __shared__ __align__(16) float2 sx2[32 * 34];  // [ci_local][px] dup {x,x}, pad 34

    const int tid = threadIdx.x;
    const int cg  = tid >> 3;          // 0..31  (4 output channels each)
    const int pg  = tid & 7;           // 0..7
    const int cp0 = cg * 2;            // co-pair base (co = 4cg .. 4cg+3)
    const int px0 = pg * 4;

    const int pix0 = blockIdx.x * 32;  // never crosses batch (9216 % 32 == 0)
    const int b    = pix0 / HW_;
    const int off0 = pix0 - b * HW_;

    unsigned long long aq[2][4] = {};  // [cp][px] -> {q[co_lo],q[co_hi]}
    unsigned long long ak[2][4] = {};

    for (int kt = 0; kt < 4; kt++) {
        // Stage weights, packed over co pairs
        for (int i = tid; i < 2048; i += 256) {
            int cp  = i >> 5;
            int cil = i & 31;
            int gci = kt * 32 + cil;
            swq[cp * 33 + cil] = make_float2(wq[(2 * cp) * 128 + gci],
                                             wq[(2 * cp + 1) * 128 + gci]);
            swk[cp * 33 + cil] = make_float2(wk[(2 * cp) * 128 + gci],
                                             wk[(2 * cp + 1) * 128 + gci]);
        }
        // Stage x, duplicated into both halves
        for (int i = tid; i < 1024; i += 256) {
            int cil = i >> 5;
            int px  = i & 31;
            float xv = x[(size_t)(b * C_ + kt * 32 + cil) * HW_ + off0 + px];
            sx2[cil * 34 + px] = make_float2(xv, xv);
        }
        __syncthreads();

        #pragma unroll
        for (int kk = 0; kk < 32; kk++) {
            const ulonglong2* xp =
                (const ulonglong2*)&sx2[kk * 34 + px0];     // 16B aligned
            ulonglong2 xa = xp[0];
            ulonglong2 xb = xp[1];
            unsigned long long xd[4] = {xa.x, xa.y, xb.x, xb.y};

            unsigned long long wq2[2], wk2[2];
            wq2[0] = *(const unsigned long long*)&swq[(cp0    ) * 33 + kk];
            wq2[1] = *(const unsigned long long*)&swq[(cp0 + 1) * 33 + kk];
            wk2[0] = *(const unsigned long long*)&swk[(cp0    ) * 33 + kk];
            wk2[1] = *(const unsigned long long*)&swk[(cp0 + 1) * 33 + kk];

            #pragma unroll
            for (int i = 0; i < 2; i++) {
                #pragma unroll
                for (int j = 0; j < 4; j++) {
                    ffma2(aq[i][j], wq2[i], xd[j]);
                    ffma2(ak[i][j], wk2[i], xd[j]);
                }
            }
        }
        __syncthreads();
    }

    // Unpack and store: co-pair i covers co = 4cg+2i (lo) and 4cg+2i+1 (hi)
    #pragma unroll
    for (int i = 0; i < 2; i++) {
        float qlo[4], qhi[4], klo[4], khi[4];
        #pragma unroll
        for (int j = 0; j < 4; j++) {
            unpack2(qlo[j], qhi[j], aq[i][j]);
            unpack2(klo[j], khi[j], ak[i][j]);
        }
        int co = cg * 4 + 2 * i;
        size_t o0 = (size_t)(b * C_ + co) * HW_ + off0 + px0;
        size_t o1 = o0 + HW_;
        *(float4*)&g_q[o0] = make_float4(qlo[0], qlo[1], qlo[2], qlo[3]);
        *(float4*)&g_q[o1] = make_float4(qhi[0], qhi[1], qhi[2], qhi[3]);
        *(float4*)&g_k[o0] = make_float4(klo[0], klo[1], klo[2], klo[3]);
        *(float4*)&g_k[o1] = make_float4(khi[0], khi[1], khi[2], khi[3]);
    }
}

// ---------------------------------------------------------------------------
// Kernel 2: per-channel 7x7 window softmax attention.
// Block = (b, c, 16x32 pixel tile). 128 threads, each owns a 4-pixel strip.
// k/v tile (3-halo, zero-filled OOB) staged in smem; rows read as float4.
// exp via single MUFU (fold log2e into q). Register-lean for occupancy.
// ---------------------------------------------------------------------------
#define TH 16
#define TW 32
#define HALO_R (TH + 6)   // 22
#define HALO_C (TW + 6)   // 38
#define SROW   40         // padded smem row stride

__global__ __launch_bounds__(128, 8) void attn_kernel(
    const float* __restrict__ v_g,
    const float* __restrict__ rel_h,
    const float* __restrict__ rel_w,
    float* __restrict__ out)
{
    __shared__ __align__(16) float skm[HALO_R * SROW];
    __shared__ __align__(16) float svm[HALO_R * SROW];

    const int tid  = threadIdx.x;
    const int c    = blockIdx.y;
    const int b    = blockIdx.z;
    const int tile = blockIdx.x;          // 0..17
    const int tx   = tile % 3;
    const int ty   = tile / 3;
    const int w0   = tx * TW;
    const int h0   = ty * TH;

    const size_t imgoff = (size_t)(b * C_ + c) * HW_;
    const float* kimg = g_k + imgoff;
    const float* vimg = v_g + imgoff;

    // Stage haloed k/v tile (zero-fill OOB == pad-then-unfold semantics)
    for (int i = tid; i < HALO_R * HALO_C; i += 128) {
        int rr  = i / HALO_C;
        int col = i - rr * HALO_C;
        int gr  = h0 - 3 + rr;
        int gc  = w0 - 3 + col;
        bool inb = ((unsigned)gr < 96u) && ((unsigned)gc < 96u);
        float kv = 0.f, vv = 0.f;
        if (inb) {
            kv = kimg[gr * 96 + gc];
            vv = vimg[gr * 96 + gc];
        }
        skm[rr * SROW + col] = kv;
        svm[rr * SROW + col] = vv;
    }
    __syncthreads();

    const int r  = tid >> 3;            // row within tile
    const int x0 = (tid & 7) * 4;       // strip start col

    const float L2E = 1.4426950408889634f;
    float4 qv = *(const float4*)&g_q[imgoff + (size_t)(h0 + r) * 96 + w0 + x0];
    float qe[4] = {qv.x * L2E, qv.y * L2E, qv.z * L2E, qv.w * L2E};

    float s[4] = {0.f, 0.f, 0.f, 0.f};
    float a[4] = {0.f, 0.f, 0.f, 0.f};

    if (c < 64) {
        // rel depends on kh only: l = qe*k + (qe*rh[kh])
        float rh[7];
        #pragma unroll
        for (int j = 0; j < 7; j++) rh[j] = rel_h[c * 7 + j];

        #pragma unroll
        for (int kh = 0; kh < 7; kh++) {
            int base = (r + kh) * SROW + x0;
            float4 k0 = *(const float4*)&skm[base];
            float4 k1 = *(const float4*)&skm[base + 4];
            float4 k2 = *(const float4*)&skm[base + 8];
            float4 v0 = *(const float4*)&svm[base];
            float4 v1 = *(const float4*)&svm[base + 4];
            float4 v2 = *(const float4*)&svm[base + 8];
            float kf[10] = {k0.x,k0.y,k0.z,k0.w,k1.x,k1.y,k1.z,k1.w,k2.x,k2.y};
            float vf[10] = {v0.x,v0.y,v0.z,v0.w,v1.x,v1.y,v1.z,v1.w,v2.x,v2.y};
            float rrq[4];
            #pragma unroll
            for (int p = 0; p < 4; p++) rrq[p] = qe[p] * rh[kh];
            #pragma unroll
            for (int j = 0; j < 7; j++) {
                #pragma unroll
                for (int p = 0; p < 4; p++) {
                    float l = fmaf(qe[p], kf[p + j], rrq[p]);
                    float e;
                    asm("ex2.approx.ftz.f32 %0, %1;" : "=f"(e) : "f"(l));
                    s[p] += e;
                    a[p] = fmaf(e, vf[p + j], a[p]);
                }
            }
        }
    } else {
        // rel depends on kw only: l = qe * (k + rw[j])   (register-lean)
        float rw[7];
        #pragma unroll
        for (int j = 0; j < 7; j++) rw[j] = rel_w[(c - 64) * 7 + j];

        #pragma unroll
        for (int kh = 0; kh < 7; kh++) {
            int base = (r + kh) * SROW + x0;
            float4 k0 = *(const float4*)&skm[base];
            float4 k1 = *(const float4*)&skm[base + 4];
            float4 k2 = *(const float4*)&skm[base + 8];
            float4 v0 = *(const float4*)&svm[base];
            float4 v1 = *(const float4*)&svm[base + 4];
            float4 v2 = *(const float4*)&svm[base + 8];
            float kf[10] = {k0.x,k0.y,k0.z,k0.w,k1.x,k1.y,k1.z,k1.w,k2.x,k2.y};
            float vf[10] = {v0.x,v0.y,v0.z,v0.w,v1.x,v1.y,v1.z,v1.w,v2.x,v2.y};
            #pragma unroll
            for (int j = 0; j < 7; j++) {
                #pragma unroll
                for (int p = 0; p < 4; p++) {
                    float l = qe[p] * (kf[p + j] + rw[j]);
                    float e;
                    asm("ex2.approx.ftz.f32 %0, %1;" : "=f"(e) : "f"(l));
                    s[p] += e;
                    a[p] = fmaf(e, vf[p + j], a[p]);
                }
            }
        }
    }

    float4 o;
    o.x = __fdividef(a[0], s[0]);
    o.y = __fdividef(a[1], s[1]);
    o.z = __fdividef(a[2], s[2]);
    o.w = __fdividef(a[3], s[3]);
    *(float4*)&out[imgoff + (size_t)(h0 + r) * 96 + w0 + x0] = o;
}

// ---------------------------------------------------------------------------
// Launch
// ---------------------------------------------------------------------------
extern "C" void kernel_launch(void* const* d_in, const int* in_sizes, int n_in,
                              void* d_out, int out_size)
{
    const float* x     = (const float*)d_in[0];
    const float* v     = (const float*)d_in[1];
    const float* wq    = (const float*)d_in[2];
    const float* wk    = (const float*)d_in[3];
    const float* rel_h = (const float*)d_in[4];
    const float* rel_w = (const float*)d_in[5];
    float* out = (float*)d_out;

    qk_gemm_kernel<<<NPIX / 32, 256>>>(x, wq, wk);

    dim3 grid(18, C_, B_);   // 18 tiles of 16x32 per (b,c)
    attn_kernel<<<grid, 128>>>(v, rel_h, rel_w, out);
}

// round 4
// speedup vs baseline: 1.6774x; 1.6774x over previous
#include <cuda_runtime.h>
#include <cuda_bf16.h>
#include <cstdint>

#define B_   2
#define C_   128
#define H_   96
#define W_   96
#define HW_  9216     // 96*96
#define NPIX 18432    // B*H*W

#define STRW 68                    // padded row stride in 32-bit words (136 bf16)
#define TILE_WORDS (128 * STRW)    // 8704 words = 34816 B per operand tile

// Scratch (allocation-free rule: __device__ globals)
__device__ __align__(16) float g_q[B_ * C_ * HW_];
__device__ __align__(16) float g_k[B_ * C_ * HW_];
// Pre-split bf16 weight images, already in the padded smem layout (word = co*68 + ci_pair)
__device__ __align__(16) uint32_t g_wqh[TILE_WORDS];
__device__ __align__(16) uint32_t g_wql[TILE_WORDS];
__device__ __align__(16) uint32_t g_wkh[TILE_WORDS];
__device__ __align__(16) uint32_t g_wkl[TILE_WORDS];

// ---------------------------------------------------------------------------
// bf16 hi/lo split helpers
// ---------------------------------------------------------------------------
__device__ __forceinline__ uint32_t pack_hi(float a0, float a1) {
    __nv_bfloat162 h;
    h.x = __float2bfloat16(a0);
    h.y = __float2bfloat16(a1);
    return *(uint32_t*)&h;
}
__device__ __forceinline__ uint32_t pack_lo(float a0, float a1) {
    __nv_bfloat16 h0 = __float2bfloat16(a0);
    __nv_bfloat16 h1 = __float2bfloat16(a1);
    __nv_bfloat162 l;
    l.x = __float2bfloat16(a0 - __bfloat162float(h0));
    l.y = __float2bfloat16(a1 - __bfloat162float(h1));
    return *(uint32_t*)&l;
}

__device__ __forceinline__ void mma16816(float* d, uint32_t a0, uint32_t a1,
                                         uint32_t a2, uint32_t a3,
                                         uint32_t b0, uint32_t b1) {
    asm volatile(
        "mma.sync.aligned.m16n8k16.row.col.f32.bf16.bf16.f32 "
        "{%0,%1,%2,%3}, {%4,%5,%6,%7}, {%8,%9}, {%0,%1,%2,%3};"
        : "+f"(d[0]), "+f"(d[1]), "+f"(d[2]), "+f"(d[3])
        : "r"(a0), "r"(a1), "r"(a2), "r"(a3), "r"(b0), "r"(b1));
}

// ---------------------------------------------------------------------------
// Kernel 0: split weights into bf16 hi/lo in the padded layout.
// ---------------------------------------------------------------------------
__global__ __launch_bounds__(256) void wsplit_kernel(
    const float* __restrict__ wq, const float* __restrict__ wk)
{
    int i = blockIdx.x * 256 + threadIdx.x;   // 0..8191 = (co, ci_pair)
    if (i >= 128 * 64) return;
    int co = i >> 6;
    int cp = i & 63;
    int off = co * STRW + cp;

    float a0 = wq[co * 128 + 2 * cp], a1 = wq[co * 128 + 2 * cp + 1];
    float b0 = wk[co * 128 + 2 * cp], b1 = wk[co * 128 + 2 * cp + 1];
    g_wqh[off] = pack_hi(a0, a1);
    g_wql[off] = pack_lo(a0, a1);
    g_wkh[off] = pack_hi(b0, b1);
    g_wkl[off] = pack_lo(b0, b1);
}

// ---------------------------------------------------------------------------
// Kernel 1: q = Wq @ x, k = Wk @ x via mma.sync bf16 split-GEMM.
// Per CTA: 128 px x 128 co of BOTH q and k. Warps 0-3 -> q, warps 4-7 -> k.
// Each warp: 64x64 output (4 m16 tiles x 8 n8 tiles), 3 passes (hh, h*lo, lo*h).
// ---------------------------------------------------------------------------
#define SM_WQH 0
#define SM_WQL (TILE_WORDS)
#define SM_WKH (2 * TILE_WORDS)
#define SM_WKL (3 * TILE_WORDS)
#define SM_XH  (4 * TILE_WORDS)
#define SM_XL  (5 * TILE_WORDS)
#define SM_TOTAL_BYTES (6 * TILE_WORDS * 4)   // 208896 B

__global__ __launch_bounds__(256, 1) void qk_mma_kernel(const float* __restrict__ x)
{
    extern __shared__ __align__(16) uint32_t smw[];
    const int tid  = threadIdx.x;
    const int lane = tid & 31;
    const int wid  = tid >> 5;

    const int px0  = blockIdx.x * 128;     // 9216 % 128 == 0: never crosses batch
    const int b    = px0 / HW_;
    const int off0 = px0 - b * HW_;

    // ---- Stage weights (pre-laid-out): straight vector copy ----
    {
        const uint4* s = (const uint4*)g_wqh;   // 4 contiguous arrays? no - copy each
        uint4* d;
        const uint4* srcs[4] = {(const uint4*)g_wqh, (const uint4*)g_wql,
                                (const uint4*)g_wkh, (const uint4*)g_wkl};
        uint32_t dsts[4] = {SM_WQH, SM_WQL, SM_WKH, SM_WKL};
        #pragma unroll
        for (int bu = 0; bu < 4; bu++) {
            s = srcs[bu];
            d = (uint4*)&smw[dsts[bu]];
            for (int i = tid; i < TILE_WORDS / 4; i += 256)
                d[i] = s[i];
        }
    }

    // ---- Stage x tile: [px][ci] bf16 hi/lo, padded stride, conflict-free ----
    // gidx bits: [0:3)=p_lo, [3:5)=cp_lo, [5:9)=p_hi, [9:13)=cp_hi
    for (int it = 0; it < 32; it++) {
        int gidx = it * 256 + tid;
        int p  = (gidx & 7) | (((gidx >> 5) & 15) << 3);
        int cp = ((gidx >> 3) & 3) | ((gidx >> 9) << 2);
        const float* xp = x + (size_t)(b * C_ + 2 * cp) * HW_ + off0 + p;
        float a0 = xp[0];
        float a1 = xp[HW_];
        int off = p * STRW + cp;
        smw[SM_XH + off] = pack_hi(a0, a1);
        smw[SM_XL + off] = pack_lo(a0, a1);
    }
    __syncthreads();

    // ---- Warp mainloop ----
    const int mat = wid >> 2;          // 0 = q, 1 = k
    const int wm  = wid & 1;           // M half
    const int wn  = (wid >> 1) & 1;    // N half
    const int gid = lane >> 2;
    const int tg  = lane & 3;

    const uint32_t* Ahi = &smw[mat ? SM_WKH : SM_WQH];
    const uint32_t* Alo = &smw[mat ? SM_WKL : SM_WQL];
    const uint32_t* Xh  = &smw[SM_XH];
    const uint32_t* Xl  = &smw[SM_XL];

    float acc[4][8][4];
    #pragma unroll
    for (int mt = 0; mt < 4; mt++)
        #pragma unroll
        for (int nt = 0; nt < 8; nt++)
            #pragma unroll
            for (int e = 0; e < 4; e++)
                acc[mt][nt][e] = 0.f;

    for (int ps = 0; ps < 3; ps++) {
        const uint32_t* A = (ps == 2) ? Alo : Ahi;
        const uint32_t* Bm = (ps == 1) ? Xl : Xh;

        for (int ks = 0; ks < 8; ks++) {
            const int ko = ks * 8 + tg;

            uint32_t bf[8][2];
            #pragma unroll
            for (int nt = 0; nt < 8; nt++) {
                int pxr = (wn * 64 + nt * 8 + gid) * STRW + ko;
                bf[nt][0] = Bm[pxr];
                bf[nt][1] = Bm[pxr + 4];
            }
            #pragma unroll
            for (int mt = 0; mt < 4; mt++) {
                int r0 = (wm * 64 + mt * 16 + gid) * STRW + ko;
                uint32_t a0 = A[r0];
                uint32_t a1 = A[r0 + 8 * STRW];
                uint32_t a2 = A[r0 + 4];
                uint32_t a3 = A[r0 + 8 * STRW + 4];
                #pragma unroll
                for (int nt = 0; nt < 8; nt++)
                    mma16816(acc[mt][nt], a0, a1, a2, a3, bf[nt][0], bf[nt][1]);
            }
        }
    }

    // ---- Epilogue: registers -> global (float2 per half-row) ----
    float* gd = mat ? g_k : g_q;
    #pragma unroll
    for (int mt = 0; mt < 4; mt++) {
        int co = wm * 64 + mt * 16 + gid;
        size_t rb0 = (size_t)(b * C_ + co) * HW_ + off0;
        size_t rb1 = rb0 + (size_t)8 * HW_;
        #pragma unroll
        for (int nt = 0; nt < 8; nt++) {
            int px = wn * 64 + nt * 8 + 2 * tg;
            *(float2*)&gd[rb0 + px] = make_float2(acc[mt][nt][0], acc[mt][nt][1]);
            *(float2*)&gd[rb1 + px] = make_float2(acc[mt][nt][2], acc[mt][nt][3]);
        }
    }
}

// ---------------------------------------------------------------------------
// Kernel 2: per-channel 7x7 window softmax attention (round-1 version).
// ---------------------------------------------------------------------------
#define TH 16
#define TW 32
#define HALO_R (TH + 6)
#define HALO_C (TW + 6)
#define SROW   40

__global__ __launch_bounds__(128) void attn_kernel(
    const float* __restrict__ v_g,
    const float* __restrict__ rel_h,
    const float* __restrict__ rel_w,
    float* __restrict__ out)
{
    __shared__ __align__(16) float skm[HALO_R * SROW];
    __shared__ __align__(16) float svm[HALO_R * SROW];

    const int tid  = threadIdx.x;
    const int c    = blockIdx.y;
    const int b    = blockIdx.z;
    const int tile = blockIdx.x;
    const int tx   = tile % 3;
    const int ty   = tile / 3;
    const int w0   = tx * TW;
    const int h0   = ty * TH;

    const size_t imgoff = (size_t)(b * C_ + c) * HW_;
    const float* kimg = g_k + imgoff;
    const float* vimg = v_g + imgoff;

    for (int i = tid; i < HALO_R * HALO_C; i += 128) {
        int rr  = i / HALO_C;
        int col = i - rr * HALO_C;
        int gr  = h0 - 3 + rr;
        int gc  = w0 - 3 + col;
        bool inb = ((unsigned)gr < 96u) && ((unsigned)gc < 96u);
        float kv = 0.f, vv = 0.f;
        if (inb) {
            kv = kimg[gr * 96 + gc];
            vv = vimg[gr * 96 + gc];
        }
        skm[rr * SROW + col] = kv;
        svm[rr * SROW + col] = vv;
    }
    __syncthreads();

    const int r  = tid >> 3;
    const int x0 = (tid & 7) * 4;

    const float L2E = 1.4426950408889634f;
    float4 qv = *(const float4*)&g_q[imgoff + (size_t)(h0 + r) * 96 + w0 + x0];
    float qe[4] = {qv.x * L2E, qv.y * L2E, qv.z * L2E, qv.w * L2E};

    float s[4] = {0.f, 0.f, 0.f, 0.f};
    float a[4] = {0.f, 0.f, 0.f, 0.f};

    if (c < 64) {
        float rh[7];
        #pragma unroll
        for (int j = 0; j < 7; j++) rh[j] = rel_h[c * 7 + j];

        #pragma unroll
        for (int kh = 0; kh < 7; kh++) {
            int base = (r + kh) * SROW + x0;
            float4 k0 = *(const float4*)&skm[base];
            float4 k1 = *(const float4*)&skm[base + 4];
            float4 k2 = *(const float4*)&skm[base + 8];
            float4 v0 = *(const float4*)&svm[base];
            float4 v1 = *(const float4*)&svm[base + 4];
            float4 v2 = *(const float4*)&svm[base + 8];
            float kf[10] = {k0.x,k0.y,k0.z,k0.w,k1.x,k1.y,k1.z,k1.w,k2.x,k2.y};
            float vf[10] = {v0.x,v0.y,v0.z,v0.w,v1.x,v1.y,v1.z,v1.w,v2.x,v2.y};
            float rrq[4];
            #pragma unroll
            for (int p = 0; p < 4; p++) rrq[p] = qe[p] * rh[kh];
            #pragma unroll
            for (int j = 0; j < 7; j++) {
                #pragma unroll
                for (int p = 0; p < 4; p++) {
                    float l = fmaf(qe[p], kf[p + j], rrq[p]);
                    float e;
                    asm("ex2.approx.ftz.f32 %0, %1;" : "=f"(e) : "f"(l));
                    s[p] += e;
                    a[p] = fmaf(e, vf[p + j], a[p]);
                }
            }
        }
    } else {
        float rq[7][4];
        #pragma unroll
        for (int j = 0; j < 7; j++) {
            float rw = rel_w[(c - 64) * 7 + j];
            #pragma unroll
            for (int p = 0; p < 4; p++) rq[j][p] = qe[p] * rw;
        }

        #pragma unroll
        for (int kh = 0; kh < 7; kh++) {
            int base = (r + kh) * SROW + x0;
            float4 k0 = *(const float4*)&skm[base];
            float4 k1 = *(const float4*)&skm[base + 4];
            float4 k2 = *(const float4*)&skm[base + 8];
            float4 v0 = *(const float4*)&svm[base];
            float4 v1 = *(const float4*)&svm[base + 4];
            float4 v2 = *(const float4*)&svm[base + 8];
            float kf[10] = {k0.x,k0.y,k0.z,k0.w,k1.x,k1.y,k1.z,k1.w,k2.x,k2.y};
            float vf[10] = {v0.x,v0.y,v0.z,v0.w,v1.x,v1.y,v1.z,v1.w,v2.x,v2.y};
            #pragma unroll
            for (int j = 0; j < 7; j++) {
                #pragma unroll
                for (int p = 0; p < 4; p++) {
                    float l = fmaf(qe[p], kf[p + j], rq[j][p]);
                    float e;
                    asm("ex2.approx.ftz.f32 %0, %1;" : "=f"(e) : "f"(l));
                    s[p] += e;
                    a[p] = fmaf(e, vf[p + j], a[p]);
                }
            }
        }
    }

    float4 o;
    o.x = __fdividef(a[0], s[0]);
    o.y = __fdividef(a[1], s[1]);
    o.z = __fdividef(a[2], s[2]);
    o.w = __fdividef(a[3], s[3]);
    *(float4*)&out[imgoff + (size_t)(h0 + r) * 96 + w0 + x0] = o;
}

// ---------------------------------------------------------------------------
// Launch
// ---------------------------------------------------------------------------
extern "C" void kernel_launch(void* const* d_in, const int* in_sizes, int n_in,
                              void* d_out, int out_size)
{
    const float* x     = (const float*)d_in[0];
    const float* v     = (const float*)d_in[1];
    const float* wq    = (const float*)d_in[2];
    const float* wk    = (const float*)d_in[3];
    const float* rel_h = (const float*)d_in[4];
    const float* rel_w = (const float*)d_in[5];
    float* out = (float*)d_out;

    cudaFuncSetAttribute(qk_mma_kernel,
                         cudaFuncAttributeMaxDynamicSharedMemorySize, SM_TOTAL_BYTES);

    wsplit_kernel<<<32, 256>>>(wq, wk);
    qk_mma_kernel<<<NPIX / 128, 256, SM_TOTAL_BYTES>>>(x);

    dim3 grid(18, C_, B_);
    attn_kernel<<<grid, 128>>>(v, rel_h, rel_w, out);
}

// round 6
// speedup vs baseline: 1.7250x; 1.0284x over previous
#include <cuda_runtime.h>
#include <cuda_bf16.h>
#include <cstdint>

#define B_   2
#define C_   128
#define H_   96
#define W_   96
#define HW_  9216     // 96*96
#define NPIX 18432    // B*H*W

#define STRW 68                    // padded row stride in 32-bit words (136 bf16)
#define TILE_WORDS (128 * STRW)    // 8704 words per operand tile

// Scratch (allocation-free rule: __device__ globals)
__device__ __align__(16) float g_q[B_ * C_ * HW_];
__device__ __align__(16) float g_k[B_ * C_ * HW_];

// ---------------------------------------------------------------------------
// bf16 hi/lo split helpers
// ---------------------------------------------------------------------------
__device__ __forceinline__ uint32_t pack_hi(float a0, float a1) {
    __nv_bfloat162 h;
    h.x = __float2bfloat16(a0);
    h.y = __float2bfloat16(a1);
    return *(uint32_t*)&h;
}
__device__ __forceinline__ uint32_t pack_lo(float a0, float a1) {
    __nv_bfloat16 h0 = __float2bfloat16(a0);
    __nv_bfloat16 h1 = __float2bfloat16(a1);
    __nv_bfloat162 l;
    l.x = __float2bfloat16(a0 - __bfloat162float(h0));
    l.y = __float2bfloat16(a1 - __bfloat162float(h1));
    return *(uint32_t*)&l;
}

__device__ __forceinline__ void mma16816(float* d, uint32_t a0, uint32_t a1,
                                         uint32_t a2, uint32_t a3,
                                         uint32_t b0, uint32_t b1) {
    asm volatile(
        "mma.sync.aligned.m16n8k16.row.col.f32.bf16.bf16.f32 "
        "{%0,%1,%2,%3}, {%4,%5,%6,%7}, {%8,%9}, {%0,%1,%2,%3};"
        : "+f"(d[0]), "+f"(d[1]), "+f"(d[2]), "+f"(d[3])
        : "r"(a0), "r"(a1), "r"(a2), "r"(a3), "r"(b0), "r"(b1));
}

// ---------------------------------------------------------------------------
// Kernel 1: q = Wq @ x, k = Wk @ x via mma.sync bf16 split-GEMM.
// Per CTA: 128 px x 128 co of BOTH q and k. Warps 0-3 -> q, warps 4-7 -> k.
// Weight hi/lo split done in-kernel from fp32 (no separate wsplit launch).
// ---------------------------------------------------------------------------
#define SM_WQH 0
#define SM_WQL (TILE_WORDS)
#define SM_WKH (2 * TILE_WORDS)
#define SM_WKL (3 * TILE_WORDS)
#define SM_XH  (4 * TILE_WORDS)
#define SM_XL  (5 * TILE_WORDS)
#define SM_TOTAL_BYTES (6 * TILE_WORDS * 4)   // 208896 B

__global__ __launch_bounds__(256, 1) void qk_mma_kernel(
    const float* __restrict__ x,
    const float* __restrict__ wq,
    const float* __restrict__ wk)
{
    extern __shared__ __align__(16) uint32_t smw[];
    const int tid  = threadIdx.x;
    const int lane = tid & 31;
    const int wid  = tid >> 5;

    const int px0  = blockIdx.x * 128;     // 9216 % 128 == 0: never crosses batch
    const int b    = px0 / HW_;
    const int off0 = px0 - b * HW_;

    // ---- Stage weights: fp32 global -> bf16 hi/lo split in smem ----
    for (int i = tid; i < 8192; i += 256) {   // (co, ci_pair)
        int co = i >> 6;
        int cp = i & 63;
        int off = co * STRW + cp;
        float2 aq = *(const float2*)&wq[co * 128 + 2 * cp];
        float2 ak = *(const float2*)&wk[co * 128 + 2 * cp];
        smw[SM_WQH + off] = pack_hi(aq.x, aq.y);
        smw[SM_WQL + off] = pack_lo(aq.x, aq.y);
        smw[SM_WKH + off] = pack_hi(ak.x, ak.y);
        smw[SM_WKL + off] = pack_lo(ak.x, ak.y);
    }

    // ---- Stage x tile: [px][ci] bf16 hi/lo, padded stride, conflict-free ----
    for (int it = 0; it < 32; it++) {
        int gidx = it * 256 + tid;
        int p  = (gidx & 7) | (((gidx >> 5) & 15) << 3);
        int cp = ((gidx >> 3) & 3) | ((gidx >> 9) << 2);
        const float* xp = x + (size_t)(b * C_ + 2 * cp) * HW_ + off0 + p;
        float a0 = xp[0];
        float a1 = xp[HW_];
        int off = p * STRW + cp;
        smw[SM_XH + off] = pack_hi(a0, a1);
        smw[SM_XL + off] = pack_lo(a0, a1);
    }
    __syncthreads();

    // ---- Warp mainloop ----
    const int mat = wid >> 2;          // 0 = q, 1 = k
    const int wm  = wid & 1;           // M half
    const int wn  = (wid >> 1) & 1;    // N half
    const int gid = lane >> 2;
    const int tg  = lane & 3;

    const uint32_t* Ahi = &smw[mat ? SM_WKH : SM_WQH];
    const uint32_t* Alo = &smw[mat ? SM_WKL : SM_WQL];
    const uint32_t* Xh  = &smw[SM_XH];
    const uint32_t* Xl  = &smw[SM_XL];

    float acc[4][8][4];
    #pragma unroll
    for (int mt = 0; mt < 4; mt++)
        #pragma unroll
        for (int nt = 0; nt < 8; nt++)
            #pragma unroll
            for (int e = 0; e < 4; e++)
                acc[mt][nt][e] = 0.f;

    for (int ps = 0; ps < 3; ps++) {
        const uint32_t* A  = (ps == 2) ? Alo : Ahi;
        const uint32_t* Bm = (ps == 1) ? Xl : Xh;

        for (int ks = 0; ks < 8; ks++) {
            const int ko = ks * 8 + tg;

            uint32_t bf[8][2];
            #pragma unroll
            for (int nt = 0; nt < 8; nt++) {
                int pxr = (wn * 64 + nt * 8 + gid) * STRW + ko;
                bf[nt][0] = Bm[pxr];
                bf[nt][1] = Bm[pxr + 4];
            }
            #pragma unroll
            for (int mt = 0; mt < 4; mt++) {
                int r0 = (wm * 64 + mt * 16 + gid) * STRW + ko;
                uint32_t a0 = A[r0];
                uint32_t a1 = A[r0 + 8 * STRW];
                uint32_t a2 = A[r0 + 4];
                uint32_t a3 = A[r0 + 8 * STRW + 4];
                #pragma unroll
                for (int nt = 0; nt < 8; nt++)
                    mma16816(acc[mt][nt], a0, a1, a2, a3, bf[nt][0], bf[nt][1]);
            }
        }
    }

    // ---- Epilogue: registers -> global (float2 per half-row) ----
    float* gd = mat ? g_k : g_q;
    #pragma unroll
    for (int mt = 0; mt < 4; mt++) {
        int co = wm * 64 + mt * 16 + gid;
        size_t rb0 = (size_t)(b * C_ + co) * HW_ + off0;
        size_t rb1 = rb0 + (size_t)8 * HW_;
        #pragma unroll
        for (int nt = 0; nt < 8; nt++) {
            int px = wn * 64 + nt * 8 + 2 * tg;
            *(float2*)&gd[rb0 + px] = make_float2(acc[mt][nt][0], acc[mt][nt][1]);
            *(float2*)&gd[rb1 + px] = make_float2(acc[mt][nt][2], acc[mt][nt][3]);
        }
    }
}

// ---------------------------------------------------------------------------
// Kernel 2: per-channel 7x7 window softmax attention.
// 32x32 pixel tile per block (256 threads, each owns a 4-px strip).
// k/v tile (3-halo, zero-filled OOB) staged in smem; rows read as float4.
// ---------------------------------------------------------------------------
#define TH 32
#define TW 32
#define HALO_R (TH + 6)   // 38
#define HALO_C (TW + 6)   // 38
#define SROW   40

__global__ __launch_bounds__(256) void attn_kernel(
    const float* __restrict__ v_g,
    const float* __restrict__ rel_h,
    const float* __restrict__ rel_w,
    float* __restrict__ out)
{
    __shared__ __align__(16) float skm[HALO_R * SROW];
    __shared__ __align__(16) float svm[HALO_R * SROW];

    const int tid  = threadIdx.x;
    const int c    = blockIdx.y;
    const int b    = blockIdx.z;
    const int tile = blockIdx.x;          // 0..8
    const int tx   = tile % 3;
    const int ty   = tile / 3;
    const int w0   = tx * TW;
    const int h0   = ty * TH;

    const size_t imgoff = (size_t)(b * C_ + c) * HW_;
    const float* kimg = g_k + imgoff;
    const float* vimg = v_g + imgoff;

    for (int i = tid; i < HALO_R * HALO_C; i += 256) {
        int rr  = i / HALO_C;
        int col = i - rr * HALO_C;
        int gr  = h0 - 3 + rr;
        int gc  = w0 - 3 + col;
        bool inb = ((unsigned)gr < 96u) && ((unsigned)gc < 96u);
        float kv = 0.f, vv = 0.f;
        if (inb) {
            kv = kimg[gr * 96 + gc];
            vv = vimg[gr * 96 + gc];
        }
        skm[rr * SROW + col] = kv;
        svm[rr * SROW + col] = vv;
    }
    __syncthreads();

    const int r  = tid >> 3;            // 0..31 row within tile
    const int x0 = (tid & 7) * 4;       // strip start col

    const float L2E = 1.4426950408889634f;
    float4 qv = *(const float4*)&g_q[imgoff + (size_t)(h0 + r) * 96 + w0 + x0];
    float qe[4] = {qv.x * L2E, qv.y * L2E, qv.z * L2E, qv.w * L2E};

    float s[4] = {0.f, 0.f, 0.f, 0.f};
    float a[4] = {0.f, 0.f, 0.f, 0.f};

    if (c < 64) {
        float rh[7];
        #pragma unroll
        for (int j = 0; j < 7; j++) rh[j] = rel_h[c * 7 + j];

        #pragma unroll
        for (int kh = 0; kh < 7; kh++) {
            int base = (r + kh) * SROW + x0;
            float4 k0 = *(const float4*)&skm[base];
            float4 k1 = *(const float4*)&skm[base + 4];
            float4 k2 = *(const float4*)&skm[base + 8];
            float4 v0 = *(const float4*)&svm[base];
            float4 v1 = *(const float4*)&svm[base + 4];
            float4 v2 = *(const float4*)&svm[base + 8];
            float kf[10] = {k0.x,k0.y,k0.z,k0.w,k1.x,k1.y,k1.z,k1.w,k2.x,k2.y};
            float vf[10] = {v0.x,v0.y,v0.z,v0.w,v1.x,v1.y,v1.z,v1.w,v2.x,v2.y};
            float rrq[4];
            #pragma unroll
            for (int p = 0; p < 4; p++) rrq[p] = qe[p] * rh[kh];
            #pragma unroll
            for (int j = 0; j < 7; j++) {
                #pragma unroll
                for (int p = 0; p < 4; p++) {
                    float l = fmaf(qe[p], kf[p + j], rrq[p]);
                    float e;
                    asm("ex2.approx.ftz.f32 %0, %1;" : "=f"(e) : "f"(l));
                    s[p] += e;
                    a[p] = fmaf(e, vf[p + j], a[p]);
                }
            }
        }
    } else {
        float rq[7][4];
        #pragma unroll
        for (int j = 0; j < 7; j++) {
            float rw = rel_w[(c - 64) * 7 + j];
            #pragma unroll
            for (int p = 0; p < 4; p++) rq[j][p] = qe[p] * rw;
        }

        #pragma unroll
        for (int kh = 0; kh < 7; kh++) {
            int base = (r + kh) * SROW + x0;
            float4 k0 = *(const float4*)&skm[base];
            float4 k1 = *(const float4*)&skm[base + 4];
            float4 k2 = *(const float4*)&skm[base + 8];
            float4 v0 = *(const float4*)&svm[base];
            float4 v1 = *(const float4*)&svm[base + 4];
            float4 v2 = *(const float4*)&svm[base + 8];
            float kf[10] = {k0.x,k0.y,k0.z,k0.w,k1.x,k1.y,k1.z,k1.w,k2.x,k2.y};
            float vf[10] = {v0.x,v0.y,v0.z,v0.w,v1.x,v1.y,v1.z,v1.w,v2.x,v2.y};
            #pragma unroll
            for (int j = 0; j < 7; j++) {
                #pragma unroll
                for (int p = 0; p < 4; p++) {
                    float l = fmaf(qe[p], kf[p + j], rq[j][p]);
                    float e;
                    asm("ex2.approx.ftz.f32 %0, %1;" : "=f"(e) : "f"(l));
                    s[p] += e;
                    a[p] = fmaf(e, vf[p + j], a[p]);
                }
            }
        }
    }

    float4 o;
    o.x = __fdividef(a[0], s[0]);
    o.y = __fdividef(a[1], s[1]);
    o.z = __fdividef(a[2], s[2]);
    o.w = __fdividef(a[3], s[3]);
    *(float4*)&out[imgoff + (size_t)(h0 + r) * 96 + w0 + x0] = o;
}

// ---------------------------------------------------------------------------
// Launch
// ---------------------------------------------------------------------------
extern "C" void kernel_launch(void* const* d_in, const int* in_sizes, int n_in,
                              void* d_out, int out_size)
{
    const float* x     = (const float*)d_in[0];
    const float* v     = (const float*)d_in[1];
    const float* wq    = (const float*)d_in[2];
    const float* wk    = (const float*)d_in[3];
    const float* rel_h = (const float*)d_in[4];
    const float* rel_w = (const float*)d_in[5];
    float* out = (float*)d_out;

    cudaFuncSetAttribute(qk_mma_kernel,
                         cudaFuncAttributeMaxDynamicSharedMemorySize, SM_TOTAL_BYTES);

    qk_mma_kernel<<<NPIX / 128, 256, SM_TOTAL_BYTES>>>(x, wq, wk);

    dim3 grid(9, C_, B_);   // 9 tiles of 32x32 per (b,c)
    attn_kernel<<<grid, 256>>>(v, rel_h, rel_w, out);
}